// round 6
// baseline (speedup 1.0000x reference)
#include <cuda_runtime.h>

// ---------------------------------------------------------------------------
// QuantumNeuralNetwork: fused MLP -> 4-qubit circuit -> classifier.
//
// R1: quantum circuit reduced to fixed 16x16 real symmetric M (prelude kernel);
//     <Z0> = v^T M v with v = kron_i (cos f_i/2, sin f_i/2).
// R2: packed fp32x2 (fma.rn.f32x2) — 2 samples per thread in 64-bit register
//     pairs; weights duplicated {w,w} in shared so one LDS.128 feeds 2 FFMA2.
//     + input prefetch one k-iteration ahead.
// ---------------------------------------------------------------------------

typedef unsigned long long ull;

__device__ float g_M[256];   // Re(U^H Z0 U), 16x16

// -------------------- f32x2 helpers ----------------------------------------
__device__ __forceinline__ ull pack2(float lo, float hi) {
    ull p;
    asm("mov.b64 %0, {%1, %2};" : "=l"(p)
        : "r"(__float_as_uint(lo)), "r"(__float_as_uint(hi)));
    return p;
}
__device__ __forceinline__ void unpack2(ull p, float& lo, float& hi) {
    unsigned a, b;
    asm("mov.b64 {%0, %1}, %2;" : "=r"(a), "=r"(b) : "l"(p));
    lo = __uint_as_float(a); hi = __uint_as_float(b);
}
__device__ __forceinline__ ull dup2(float x) { return pack2(x, x); }
__device__ __forceinline__ ull fma2(ull a, ull b, ull c) {
    ull d;
    asm("fma.rn.f32x2 %0, %1, %2, %3;" : "=l"(d) : "l"(a), "l"(b), "l"(c));
    return d;
}
__device__ __forceinline__ ull relu2(ull p) {
    float lo, hi; unpack2(p, lo, hi);
    return pack2(fmaxf(lo, 0.0f), fmaxf(hi, 0.0f));
}

// -------------------- prelude: build M from qweights -----------------------
__global__ void build_M_kernel(const float* __restrict__ qw /* [2][4][3] */) {
    __shared__ float Ur[16][16];
    __shared__ float Ui[16][16];
    int t = threadIdx.x;               // 256 threads

    {   int z = t >> 4, c = t & 15;
        Ur[z][c] = (z == c) ? 1.0f : 0.0f;
        Ui[z][c] = 0.0f; }
    __syncthreads();

    for (int l = 0; l < 2; l++) {
        for (int i = 0; i < 4; i++) {
            float phi   = qw[(l * 4 + i) * 3 + 0];
            float theta = qw[(l * 4 + i) * 3 + 1];
            float omega = qw[(l * 4 + i) * 3 + 2];
            float ct, st;  sincosf(0.5f * theta, &st, &ct);
            float ap = 0.5f * (phi + omega), am = 0.5f * (phi - omega);
            float cap, sap, cam, sam;
            sincosf(ap, &sap, &cap);
            sincosf(am, &sam, &cam);
            float g00r =  cap * ct, g00i = -sap * ct;
            float g01r = -cam * st, g01i = -sam * st;
            float g10r =  cam * st, g10i = -sam * st;
            float g11r =  cap * ct, g11i =  sap * ct;

            int p = 3 - i;
            int mask = 1 << p;
            if (t < 128) {
                int pr = t >> 4, c = t & 15;
                int z0 = ((pr >> p) << (p + 1)) | (pr & (mask - 1));
                int z1 = z0 | mask;
                float ar = Ur[z0][c], ai = Ui[z0][c];
                float br = Ur[z1][c], bi = Ui[z1][c];
                Ur[z0][c] = g00r * ar - g00i * ai + g01r * br - g01i * bi;
                Ui[z0][c] = g00r * ai + g00i * ar + g01r * bi + g01i * br;
                Ur[z1][c] = g10r * ar - g10i * ai + g11r * br - g11i * bi;
                Ui[z1][c] = g10r * ai + g10i * ar + g11r * bi + g11i * br;
            }
            __syncthreads();
        }
        {   int z = t >> 4, c = t & 15;
            int neg = 0;
            for (int i = 0; i < 3; i++) {
                int mA = 1 << (3 - i), mB = 1 << (2 - i);
                if ((z & mA) && (z & mB)) neg ^= 1;
            }
            if (neg) { Ur[z][c] = -Ur[z][c]; Ui[z][c] = -Ui[z][c]; } }
        __syncthreads();
    }

    {   int a = t >> 4, b = t & 15;
        float m = 0.0f;
        #pragma unroll
        for (int z = 0; z < 16; z++) {
            float d = (z & 8) ? -1.0f : 1.0f;
            m += d * (Ur[z][a] * Ur[z][b] + Ui[z][a] * Ui[z][b]);
        }
        g_M[a * 16 + b] = m; }
}

// -------------------- main fused kernel (2 samples / thread) ---------------
__global__ __launch_bounds__(128, 3)
void qnn_kernel(const float* __restrict__ text, const float* __restrict__ image,
                const float* __restrict__ tW1, const float* __restrict__ tb1,
                const float* __restrict__ tW2, const float* __restrict__ tb2,
                const float* __restrict__ iW1, const float* __restrict__ ib1,
                const float* __restrict__ iW2, const float* __restrict__ ib2,
                const float* __restrict__ cW1, const float* __restrict__ cb1,
                const float* __restrict__ cW2, const float* __restrict__ cb2,
                float* __restrict__ out, int B)
{
    // all weight arrays duplicated {w,w} as 64-bit pairs
    __shared__ __align__(16) ull s_iW1d[3072];   // [48][64]
    __shared__ __align__(16) ull s_tW1d[512];    // [16][32]
    __shared__ __align__(16) ull s_iW2d[256];    // [64][4]
    __shared__ __align__(16) ull s_tW2d[128];    // [32][4]
    __shared__ __align__(16) ull s_M2[256];      // [16][16]
    __shared__ ull s_ib1d[64], s_tb1d[32];
    __shared__ ull s_cW1d[16], s_cb1d[16], s_cW2d[32];
    __shared__ ull s_fbd[4];
    __shared__ float s_cb2[2];

    int tid = threadIdx.x;
    for (int i = tid; i < 3072; i += 128) s_iW1d[i] = dup2(iW1[i]);
    for (int i = tid; i < 512;  i += 128) s_tW1d[i] = dup2(tW1[i]);
    for (int i = tid; i < 256;  i += 128) { s_iW2d[i] = dup2(iW2[i]); s_M2[i] = dup2(g_M[i]); }
    if (tid < 128) s_tW2d[tid] = dup2(tW2[tid]);
    if (tid < 64)  s_ib1d[tid] = dup2(ib1[tid]);
    if (tid < 32)  { s_tb1d[tid] = dup2(tb1[tid]); s_cW2d[tid] = dup2(cW2[tid]); }
    if (tid < 16)  { s_cW1d[tid] = dup2(cW1[tid]); s_cb1d[tid] = dup2(cb1[tid]); }
    if (tid < 4)   s_fbd[tid] = dup2(tb2[tid] + ib2[tid]);
    if (tid < 2)   s_cb2[tid] = cb2[tid];
    __syncthreads();

    int s0 = blockIdx.x * 256 + tid;
    int s1 = s0 + 128;
    if (s0 >= B) return;
    bool has1 = (s1 < B);
    int s1c = has1 ? s1 : s0;

    ull fe[4];
    #pragma unroll
    for (int c = 0; c < 4; c++) fe[c] = s_fbd[c];

    // ---- image MLP: 48 -> relu(64) -> 4, j-tiled 2 x 32, prefetched ----
    {
        const float4* ip0 = reinterpret_cast<const float4*>(image) + (size_t)s0  * 12;
        const float4* ip1 = reinterpret_cast<const float4*>(image) + (size_t)s1c * 12;
        #pragma unroll
        for (int chunk = 0; chunk < 2; chunk++) {
            int wb = chunk * 32;
            ull acc[32];
            #pragma unroll
            for (int j = 0; j < 32; j++) acc[j] = s_ib1d[wb + j];
            float4 n0 = __ldg(ip0);
            float4 n1 = __ldg(ip1);
            #pragma unroll 1
            for (int kk = 0; kk < 12; kk++) {
                float4 a0 = n0, a1 = n1;
                if (kk + 1 < 12) { n0 = __ldg(ip0 + kk + 1); n1 = __ldg(ip1 + kk + 1); }
                ull ap[4] = { pack2(a0.x, a1.x), pack2(a0.y, a1.y),
                              pack2(a0.z, a1.z), pack2(a0.w, a1.w) };
                #pragma unroll
                for (int dk = 0; dk < 4; dk++) {
                    const ulonglong2* w2 =
                        reinterpret_cast<const ulonglong2*>(&s_iW1d[(kk * 4 + dk) * 64 + wb]);
                    #pragma unroll
                    for (int j2 = 0; j2 < 16; j2++) {
                        ulonglong2 w = w2[j2];
                        acc[2 * j2]     = fma2(ap[dk], w.x, acc[2 * j2]);
                        acc[2 * j2 + 1] = fma2(ap[dk], w.y, acc[2 * j2 + 1]);
                    }
                }
            }
            #pragma unroll
            for (int j = 0; j < 32; j++) {
                ull h = relu2(acc[j]);
                const ulonglong2* wv =
                    reinterpret_cast<const ulonglong2*>(&s_iW2d[(wb + j) * 4]);
                ulonglong2 wa = wv[0], wbp = wv[1];
                fe[0] = fma2(h, wa.x,  fe[0]);
                fe[1] = fma2(h, wa.y,  fe[1]);
                fe[2] = fma2(h, wbp.x, fe[2]);
                fe[3] = fma2(h, wbp.y, fe[3]);
            }
        }
    }

    // ---- text MLP: 16 -> relu(32) -> 4 ----
    {
        const float4* tp0 = reinterpret_cast<const float4*>(text) + (size_t)s0  * 4;
        const float4* tp1 = reinterpret_cast<const float4*>(text) + (size_t)s1c * 4;
        ull acc[32];
        #pragma unroll
        for (int j = 0; j < 32; j++) acc[j] = s_tb1d[j];
        float4 n0 = __ldg(tp0);
        float4 n1 = __ldg(tp1);
        #pragma unroll 1
        for (int kk = 0; kk < 4; kk++) {
            float4 a0 = n0, a1 = n1;
            if (kk + 1 < 4) { n0 = __ldg(tp0 + kk + 1); n1 = __ldg(tp1 + kk + 1); }
            ull ap[4] = { pack2(a0.x, a1.x), pack2(a0.y, a1.y),
                          pack2(a0.z, a1.z), pack2(a0.w, a1.w) };
            #pragma unroll
            for (int dk = 0; dk < 4; dk++) {
                const ulonglong2* w2 =
                    reinterpret_cast<const ulonglong2*>(&s_tW1d[(kk * 4 + dk) * 32]);
                #pragma unroll
                for (int j2 = 0; j2 < 16; j2++) {
                    ulonglong2 w = w2[j2];
                    acc[2 * j2]     = fma2(ap[dk], w.x, acc[2 * j2]);
                    acc[2 * j2 + 1] = fma2(ap[dk], w.y, acc[2 * j2 + 1]);
                }
            }
        }
        #pragma unroll
        for (int j = 0; j < 32; j++) {
            ull h = relu2(acc[j]);
            const ulonglong2* wv =
                reinterpret_cast<const ulonglong2*>(&s_tW2d[j * 4]);
            ulonglong2 wa = wv[0], wbp = wv[1];
            fe[0] = fma2(h, wa.x,  fe[0]);
            fe[1] = fma2(h, wa.y,  fe[1]);
            fe[2] = fma2(h, wbp.x, fe[2]);
            fe[3] = fma2(h, wbp.y, fe[3]);
        }
    }

    // ---- quantum: <Z0> = v^T M v per sample, v = kron of (cos, sin) pairs ----
    // ref half-angle of (tf+imf)*0.5 -> angle * 0.25
    ull vp[16];
    {
        float fl[4], fh[4];
        #pragma unroll
        for (int i = 0; i < 4; i++) unpack2(fe[i], fl[i], fh[i]);
        float vlo[16], vhi[16];
        {
            float cq[4], sq[4];
            #pragma unroll
            for (int i = 0; i < 4; i++) sincosf(fl[i] * 0.25f, &sq[i], &cq[i]);
            float p0[4] = {cq[0]*cq[1], cq[0]*sq[1], sq[0]*cq[1], sq[0]*sq[1]};
            float p1[4] = {cq[2]*cq[3], cq[2]*sq[3], sq[2]*cq[3], sq[2]*sq[3]};
            #pragma unroll
            for (int h = 0; h < 4; h++)
                #pragma unroll
                for (int lo = 0; lo < 4; lo++) vlo[h * 4 + lo] = p0[h] * p1[lo];
        }
        {
            float cq[4], sq[4];
            #pragma unroll
            for (int i = 0; i < 4; i++) sincosf(fh[i] * 0.25f, &sq[i], &cq[i]);
            float p0[4] = {cq[0]*cq[1], cq[0]*sq[1], sq[0]*cq[1], sq[0]*sq[1]};
            float p1[4] = {cq[2]*cq[3], cq[2]*sq[3], sq[2]*cq[3], sq[2]*sq[3]};
            #pragma unroll
            for (int h = 0; h < 4; h++)
                #pragma unroll
                for (int lo = 0; lo < 4; lo++) vhi[h * 4 + lo] = p0[h] * p1[lo];
        }
        #pragma unroll
        for (int j = 0; j < 16; j++) vp[j] = pack2(vlo[j], vhi[j]);
    }

    ull q = dup2(0.0f);
    #pragma unroll
    for (int a = 0; a < 16; a++) {
        ull w = dup2(0.0f);
        const ulonglong2* mrow = reinterpret_cast<const ulonglong2*>(&s_M2[a * 16]);
        #pragma unroll
        for (int j2 = 0; j2 < 8; j2++) {
            ulonglong2 m = mrow[j2];
            w = fma2(vp[2 * j2],     m.x, w);
            w = fma2(vp[2 * j2 + 1], m.y, w);
        }
        q = fma2(vp[a], w, q);
    }

    // ---- classifier: 1 -> relu(16) -> 2 ----
    ull o0 = dup2(s_cb2[0]);
    ull o1 = dup2(s_cb2[1]);
    #pragma unroll
    for (int j = 0; j < 16; j++) {
        ull h = relu2(fma2(q, s_cW1d[j], s_cb1d[j]));
        o0 = fma2(h, s_cW2d[2 * j],     o0);
        o1 = fma2(h, s_cW2d[2 * j + 1], o1);
    }

    float a0, b0, a1, b1;
    unpack2(o0, a0, b0);
    unpack2(o1, a1, b1);
    float2* out2 = reinterpret_cast<float2*>(out);
    out2[s0] = make_float2(a0, a1);
    if (has1) out2[s1] = make_float2(b0, b1);
}

// -------------------- launch -----------------------------------------------
extern "C" void kernel_launch(void* const* d_in, const int* in_sizes, int n_in,
                              void* d_out, int out_size) {
    const float* text = (const float*)d_in[0];
    const float* image= (const float*)d_in[1];
    const float* tW1  = (const float*)d_in[2];
    const float* tb1  = (const float*)d_in[3];
    const float* tW2  = (const float*)d_in[4];
    const float* tb2  = (const float*)d_in[5];
    const float* iW1  = (const float*)d_in[6];
    const float* ib1  = (const float*)d_in[7];
    const float* iW2  = (const float*)d_in[8];
    const float* ib2  = (const float*)d_in[9];
    const float* qw   = (const float*)d_in[10];
    const float* cW1  = (const float*)d_in[11];
    const float* cb1  = (const float*)d_in[12];
    const float* cW2  = (const float*)d_in[13];
    const float* cb2  = (const float*)d_in[14];
    float* out = (float*)d_out;

    int B = in_sizes[0] / 16;

    build_M_kernel<<<1, 256>>>(qw);
    int nblk = (B + 255) / 256;
    qnn_kernel<<<nblk, 128>>>(text, image, tW1, tb1, tW2, tb2,
                              iW1, ib1, iW2, ib2, cW1, cb1, cW2, cb2,
                              out, B);
}

// round 8
// speedup vs baseline: 1.3919x; 1.3919x over previous
#include <cuda_runtime.h>

// ---------------------------------------------------------------------------
// QuantumNeuralNetwork: fused MLP -> 4-qubit circuit -> classifier.
//
// R1: quantum circuit reduced to fixed 16x16 real symmetric M; <Z0> = v^T M v.
// R6: f32x2 packed BY ADJACENT OUTPUT j (not by sample): weights stored UNIQUE
//     in shared (one LDS.128 = 4 unique weights serving both samples of the
//     thread = 2B shared traffic per FMA-equiv, half of R1). Activations are
//     duplicated into {a,a} register pairs (1 MOV, amortized over 32 FFMA2).
// ---------------------------------------------------------------------------

typedef unsigned long long ull;

__device__ float g_M[256];   // Re(U^H Z0 U), 16x16

// -------------------- f32x2 helpers ----------------------------------------
__device__ __forceinline__ ull pack2(float lo, float hi) {
    ull p;
    asm("mov.b64 %0, {%1, %2};" : "=l"(p)
        : "r"(__float_as_uint(lo)), "r"(__float_as_uint(hi)));
    return p;
}
__device__ __forceinline__ void unpack2(ull p, float& lo, float& hi) {
    unsigned a, b;
    asm("mov.b64 {%0, %1}, %2;" : "=r"(a), "=r"(b) : "l"(p));
    lo = __uint_as_float(a); hi = __uint_as_float(b);
}
__device__ __forceinline__ ull dup2(float x) { return pack2(x, x); }
__device__ __forceinline__ ull fma2(ull a, ull b, ull c) {
    ull d;
    asm("fma.rn.f32x2 %0, %1, %2, %3;" : "=l"(d) : "l"(a), "l"(b), "l"(c));
    return d;
}
__device__ __forceinline__ ull relu2(ull p) {
    float lo, hi; unpack2(p, lo, hi);
    return pack2(fmaxf(lo, 0.0f), fmaxf(hi, 0.0f));
}

// -------------------- prelude: build M from qweights -----------------------
__global__ void build_M_kernel(const float* __restrict__ qw /* [2][4][3] */) {
    __shared__ float Ur[16][16];
    __shared__ float Ui[16][16];
    int t = threadIdx.x;               // 256 threads

    {   int z = t >> 4, c = t & 15;
        Ur[z][c] = (z == c) ? 1.0f : 0.0f;
        Ui[z][c] = 0.0f; }
    __syncthreads();

    for (int l = 0; l < 2; l++) {
        for (int i = 0; i < 4; i++) {
            float phi   = qw[(l * 4 + i) * 3 + 0];
            float theta = qw[(l * 4 + i) * 3 + 1];
            float omega = qw[(l * 4 + i) * 3 + 2];
            float ct, st;  sincosf(0.5f * theta, &st, &ct);
            float ap = 0.5f * (phi + omega), am = 0.5f * (phi - omega);
            float cap, sap, cam, sam;
            sincosf(ap, &sap, &cap);
            sincosf(am, &sam, &cam);
            float g00r =  cap * ct, g00i = -sap * ct;
            float g01r = -cam * st, g01i = -sam * st;
            float g10r =  cam * st, g10i = -sam * st;
            float g11r =  cap * ct, g11i =  sap * ct;

            int p = 3 - i;
            int mask = 1 << p;
            if (t < 128) {
                int pr = t >> 4, c = t & 15;
                int z0 = ((pr >> p) << (p + 1)) | (pr & (mask - 1));
                int z1 = z0 | mask;
                float ar = Ur[z0][c], ai = Ui[z0][c];
                float br = Ur[z1][c], bi = Ui[z1][c];
                Ur[z0][c] = g00r * ar - g00i * ai + g01r * br - g01i * bi;
                Ui[z0][c] = g00r * ai + g00i * ar + g01r * bi + g01i * br;
                Ur[z1][c] = g10r * ar - g10i * ai + g11r * br - g11i * bi;
                Ui[z1][c] = g10r * ai + g10i * ar + g11r * bi + g11i * br;
            }
            __syncthreads();
        }
        {   int z = t >> 4, c = t & 15;
            int neg = 0;
            for (int i = 0; i < 3; i++) {
                int mA = 1 << (3 - i), mB = 1 << (2 - i);
                if ((z & mA) && (z & mB)) neg ^= 1;
            }
            if (neg) { Ur[z][c] = -Ur[z][c]; Ui[z][c] = -Ui[z][c]; } }
        __syncthreads();
    }

    {   int a = t >> 4, b = t & 15;
        float m = 0.0f;
        #pragma unroll
        for (int z = 0; z < 16; z++) {
            float d = (z & 8) ? -1.0f : 1.0f;
            m += d * (Ur[z][a] * Ur[z][b] + Ui[z][a] * Ui[z][b]);
        }
        g_M[a * 16 + b] = m; }
}

// -------------------- main fused kernel (2 samples / thread) ---------------
__global__ __launch_bounds__(128, 3)
void qnn_kernel(const float* __restrict__ text, const float* __restrict__ image,
                const float* __restrict__ tW1, const float* __restrict__ tb1,
                const float* __restrict__ tW2, const float* __restrict__ tb2,
                const float* __restrict__ iW1, const float* __restrict__ ib1,
                const float* __restrict__ iW2, const float* __restrict__ ib2,
                const float* __restrict__ cW1, const float* __restrict__ cb1,
                const float* __restrict__ cW2, const float* __restrict__ cb2,
                float* __restrict__ out, int B)
{
    // UNIQUE weights in shared (no duplication)
    __shared__ __align__(16) float s_iW1[3072];   // [48][64]
    __shared__ __align__(16) float s_tW1[512];    // [16][32]
    __shared__ __align__(16) float s_iW2[256];    // [64][4]
    __shared__ __align__(16) float s_tW2[128];    // [32][4]
    __shared__ __align__(16) float s_M[256];      // [16][16]
    __shared__ __align__(16) float s_ib1[64];
    __shared__ __align__(16) float s_tb1[32];
    __shared__ float s_cW1[16], s_cb1[16], s_cW2[32];
    __shared__ float s_fb[4];
    __shared__ float s_cb2[2];

    int tid = threadIdx.x;
    for (int i = tid; i < 3072; i += 128) s_iW1[i] = iW1[i];
    for (int i = tid; i < 512;  i += 128) s_tW1[i] = tW1[i];
    for (int i = tid; i < 256;  i += 128) { s_iW2[i] = iW2[i]; s_M[i] = g_M[i]; }
    if (tid < 128) s_tW2[tid] = tW2[tid];
    if (tid < 64)  s_ib1[tid] = ib1[tid];
    if (tid < 32)  { s_tb1[tid] = tb1[tid]; s_cW2[tid] = cW2[tid]; }
    if (tid < 16)  { s_cW1[tid] = cW1[tid]; s_cb1[tid] = cb1[tid]; }
    if (tid < 4)   s_fb[tid] = tb2[tid] + ib2[tid];
    if (tid < 2)   s_cb2[tid] = cb2[tid];
    __syncthreads();

    int s0 = blockIdx.x * 256 + tid;
    int s1 = s0 + 128;
    if (s0 >= B) return;
    bool has1 = (s1 < B);
    int s1c = has1 ? s1 : s0;

    float fe0[4], fe1[4];
    #pragma unroll
    for (int c = 0; c < 4; c++) { fe0[c] = s_fb[c]; fe1[c] = s_fb[c]; }

    // ---- image MLP: 48 -> relu(64) -> 4, j-tiled 2 x 32 ----
    // acc pairs are {acc_j, acc_j+1} per sample; weights unique LDS.128.
    {
        const float4* ip0 = reinterpret_cast<const float4*>(image) + (size_t)s0  * 12;
        const float4* ip1 = reinterpret_cast<const float4*>(image) + (size_t)s1c * 12;
        #pragma unroll
        for (int chunk = 0; chunk < 2; chunk++) {
            int wb = chunk * 32;
            ull acc0[16], acc1[16];
            const ull* bias = reinterpret_cast<const ull*>(s_ib1) + wb / 2;
            #pragma unroll
            for (int j = 0; j < 16; j++) { acc0[j] = bias[j]; acc1[j] = bias[j]; }
            float4 n0 = __ldg(ip0);
            float4 n1 = __ldg(ip1);
            #pragma unroll 1
            for (int kk = 0; kk < 12; kk++) {
                float4 a0 = n0, a1 = n1;
                if (kk + 1 < 12) { n0 = __ldg(ip0 + kk + 1); n1 = __ldg(ip1 + kk + 1); }
                ull ad0[4] = { dup2(a0.x), dup2(a0.y), dup2(a0.z), dup2(a0.w) };
                ull ad1[4] = { dup2(a1.x), dup2(a1.y), dup2(a1.z), dup2(a1.w) };
                #pragma unroll
                for (int dk = 0; dk < 4; dk++) {
                    const ulonglong2* w2 = reinterpret_cast<const ulonglong2*>(
                        &s_iW1[(kk * 4 + dk) * 64 + wb]);
                    #pragma unroll
                    for (int j4 = 0; j4 < 8; j4++) {
                        ulonglong2 w = w2[j4];       // 4 unique weights
                        acc0[2 * j4]     = fma2(ad0[dk], w.x, acc0[2 * j4]);
                        acc0[2 * j4 + 1] = fma2(ad0[dk], w.y, acc0[2 * j4 + 1]);
                        acc1[2 * j4]     = fma2(ad1[dk], w.x, acc1[2 * j4]);
                        acc1[2 * j4 + 1] = fma2(ad1[dk], w.y, acc1[2 * j4 + 1]);
                    }
                }
            }
            // epilogue: relu + second layer (scalar, small)
            #pragma unroll
            for (int p = 0; p < 16; p++) {
                int j = wb + 2 * p;
                float h0lo, h0hi, h1lo, h1hi;
                unpack2(relu2(acc0[p]), h0lo, h0hi);
                unpack2(relu2(acc1[p]), h1lo, h1hi);
                const float* r0 = &s_iW2[j * 4];
                const float* r1 = &s_iW2[(j + 1) * 4];
                #pragma unroll
                for (int c = 0; c < 4; c++) {
                    fe0[c] = fmaf(h0lo, r0[c], fe0[c]);
                    fe0[c] = fmaf(h0hi, r1[c], fe0[c]);
                    fe1[c] = fmaf(h1lo, r0[c], fe1[c]);
                    fe1[c] = fmaf(h1hi, r1[c], fe1[c]);
                }
            }
        }
    }

    // ---- text MLP: 16 -> relu(32) -> 4 (single 32-j chunk) ----
    {
        const float4* tp0 = reinterpret_cast<const float4*>(text) + (size_t)s0  * 4;
        const float4* tp1 = reinterpret_cast<const float4*>(text) + (size_t)s1c * 4;
        ull acc0[16], acc1[16];
        const ull* bias = reinterpret_cast<const ull*>(s_tb1);
        #pragma unroll
        for (int j = 0; j < 16; j++) { acc0[j] = bias[j]; acc1[j] = bias[j]; }
        float4 n0 = __ldg(tp0);
        float4 n1 = __ldg(tp1);
        #pragma unroll 1
        for (int kk = 0; kk < 4; kk++) {
            float4 a0 = n0, a1 = n1;
            if (kk + 1 < 4) { n0 = __ldg(tp0 + kk + 1); n1 = __ldg(tp1 + kk + 1); }
            ull ad0[4] = { dup2(a0.x), dup2(a0.y), dup2(a0.z), dup2(a0.w) };
            ull ad1[4] = { dup2(a1.x), dup2(a1.y), dup2(a1.z), dup2(a1.w) };
            #pragma unroll
            for (int dk = 0; dk < 4; dk++) {
                const ulonglong2* w2 = reinterpret_cast<const ulonglong2*>(
                    &s_tW1[(kk * 4 + dk) * 32]);
                #pragma unroll
                for (int j4 = 0; j4 < 8; j4++) {
                    ulonglong2 w = w2[j4];
                    acc0[2 * j4]     = fma2(ad0[dk], w.x, acc0[2 * j4]);
                    acc0[2 * j4 + 1] = fma2(ad0[dk], w.y, acc0[2 * j4 + 1]);
                    acc1[2 * j4]     = fma2(ad1[dk], w.x, acc1[2 * j4]);
                    acc1[2 * j4 + 1] = fma2(ad1[dk], w.y, acc1[2 * j4 + 1]);
                }
            }
        }
        #pragma unroll
        for (int p = 0; p < 16; p++) {
            int j = 2 * p;
            float h0lo, h0hi, h1lo, h1hi;
            unpack2(relu2(acc0[p]), h0lo, h0hi);
            unpack2(relu2(acc1[p]), h1lo, h1hi);
            const float* r0 = &s_tW2[j * 4];
            const float* r1 = &s_tW2[(j + 1) * 4];
            #pragma unroll
            for (int c = 0; c < 4; c++) {
                fe0[c] = fmaf(h0lo, r0[c], fe0[c]);
                fe0[c] = fmaf(h0hi, r1[c], fe0[c]);
                fe1[c] = fmaf(h1lo, r0[c], fe1[c]);
                fe1[c] = fmaf(h1hi, r1[c], fe1[c]);
            }
        }
    }

    // ---- quantum: <Z0> = v^T M v per sample; v packed by adjacent b ----
    // ref half-angle of (tf+imf)*0.5 -> angle * 0.25
    ull vp0[8], vp1[8];
    float v0s[16], v1s[16];
    {
        float cq[4], sq[4];
        #pragma unroll
        for (int i = 0; i < 4; i++) sincosf(fe0[i] * 0.25f, &sq[i], &cq[i]);
        float p0[4] = {cq[0]*cq[1], cq[0]*sq[1], sq[0]*cq[1], sq[0]*sq[1]};
        float p1[4] = {cq[2]*cq[3], cq[2]*sq[3], sq[2]*cq[3], sq[2]*sq[3]};
        #pragma unroll
        for (int h = 0; h < 4; h++)
            #pragma unroll
            for (int lo = 0; lo < 4; lo++) v0s[h * 4 + lo] = p0[h] * p1[lo];
    }
    {
        float cq[4], sq[4];
        #pragma unroll
        for (int i = 0; i < 4; i++) sincosf(fe1[i] * 0.25f, &sq[i], &cq[i]);
        float p0[4] = {cq[0]*cq[1], cq[0]*sq[1], sq[0]*cq[1], sq[0]*sq[1]};
        float p1[4] = {cq[2]*cq[3], cq[2]*sq[3], sq[2]*cq[3], sq[2]*sq[3]};
        #pragma unroll
        for (int h = 0; h < 4; h++)
            #pragma unroll
            for (int lo = 0; lo < 4; lo++) v1s[h * 4 + lo] = p0[h] * p1[lo];
    }
    #pragma unroll
    for (int b = 0; b < 8; b++) {
        vp0[b] = pack2(v0s[2 * b], v0s[2 * b + 1]);
        vp1[b] = pack2(v1s[2 * b], v1s[2 * b + 1]);
    }

    float q0 = 0.0f, q1 = 0.0f;
    #pragma unroll
    for (int a = 0; a < 16; a++) {
        const ulonglong2* mrow = reinterpret_cast<const ulonglong2*>(&s_M[a * 16]);
        ull w0p = 0ull, w1p = 0ull;   // {0.0f, 0.0f}
        #pragma unroll
        for (int b2 = 0; b2 < 4; b2++) {
            ulonglong2 m = mrow[b2];   // 4 unique M values, reused by both samples
            w0p = fma2(vp0[2 * b2],     m.x, w0p);
            w0p = fma2(vp0[2 * b2 + 1], m.y, w0p);
            w1p = fma2(vp1[2 * b2],     m.x, w1p);
            w1p = fma2(vp1[2 * b2 + 1], m.y, w1p);
        }
        float wl, wh;
        unpack2(w0p, wl, wh);  q0 = fmaf(v0s[a], wl + wh, q0);
        unpack2(w1p, wl, wh);  q1 = fmaf(v1s[a], wl + wh, q1);
    }

    // ---- classifier: 1 -> relu(16) -> 2 (scalar per sample) ----
    float o00 = s_cb2[0], o01 = s_cb2[1];
    float o10 = s_cb2[0], o11 = s_cb2[1];
    #pragma unroll
    for (int j = 0; j < 16; j++) {
        float w1v = s_cW1[j], b1v = s_cb1[j];
        float w20 = s_cW2[2 * j], w21 = s_cW2[2 * j + 1];
        float h0 = fmaxf(fmaf(q0, w1v, b1v), 0.0f);
        float h1 = fmaxf(fmaf(q1, w1v, b1v), 0.0f);
        o00 = fmaf(h0, w20, o00);  o01 = fmaf(h0, w21, o01);
        o10 = fmaf(h1, w20, o10);  o11 = fmaf(h1, w21, o11);
    }

    float2* out2 = reinterpret_cast<float2*>(out);
    out2[s0] = make_float2(o00, o01);
    if (has1) out2[s1] = make_float2(o10, o11);
}

// -------------------- launch -----------------------------------------------
extern "C" void kernel_launch(void* const* d_in, const int* in_sizes, int n_in,
                              void* d_out, int out_size) {
    const float* text = (const float*)d_in[0];
    const float* image= (const float*)d_in[1];
    const float* tW1  = (const float*)d_in[2];
    const float* tb1  = (const float*)d_in[3];
    const float* tW2  = (const float*)d_in[4];
    const float* tb2  = (const float*)d_in[5];
    const float* iW1  = (const float*)d_in[6];
    const float* ib1  = (const float*)d_in[7];
    const float* iW2  = (const float*)d_in[8];
    const float* ib2  = (const float*)d_in[9];
    const float* qw   = (const float*)d_in[10];
    const float* cW1  = (const float*)d_in[11];
    const float* cb1  = (const float*)d_in[12];
    const float* cW2  = (const float*)d_in[13];
    const float* cb2  = (const float*)d_in[14];
    float* out = (float*)d_out;

    int B = in_sizes[0] / 16;

    build_M_kernel<<<1, 256>>>(qw);
    int nblk = (B + 255) / 256;
    qnn_kernel<<<nblk, 128>>>(text, image, tW1, tb1, tW2, tb2,
                              iW1, ib1, iW2, ib2, cW1, cb1, cW2, cb2,
                              out, B);
}

// round 11
// speedup vs baseline: 1.4166x; 1.0178x over previous
#include <cuda_runtime.h>

// ---------------------------------------------------------------------------
// QuantumNeuralNetwork: fused MLP -> 4-qubit circuit -> classifier.
//
// R1: quantum circuit reduced to fixed 16x16 real symmetric M; <Z0> = v^T M v.
// R6: f32x2 packed by adjacent output j; unique weights in shared.
// R8: 4 samples/thread (j-tile 32 kept, 2 chunks): each unique-weight LDS.128
//     now feeds 4 samples = 16 FMA-equiv (1B shared traffic per FMA-equiv).
//     Input re-read count unchanged vs R6. __launch_bounds__(128,2) to hold
//     ~128 accumulator regs without spilling.
// ---------------------------------------------------------------------------

typedef unsigned long long ull;

__device__ float g_M[256];   // Re(U^H Z0 U), 16x16

// -------------------- f32x2 helpers ----------------------------------------
__device__ __forceinline__ ull pack2(float lo, float hi) {
    ull p;
    asm("mov.b64 %0, {%1, %2};" : "=l"(p)
        : "r"(__float_as_uint(lo)), "r"(__float_as_uint(hi)));
    return p;
}
__device__ __forceinline__ void unpack2(ull p, float& lo, float& hi) {
    unsigned a, b;
    asm("mov.b64 {%0, %1}, %2;" : "=r"(a), "=r"(b) : "l"(p));
    lo = __uint_as_float(a); hi = __uint_as_float(b);
}
__device__ __forceinline__ ull dup2(float x) { return pack2(x, x); }
__device__ __forceinline__ ull fma2(ull a, ull b, ull c) {
    ull d;
    asm("fma.rn.f32x2 %0, %1, %2, %3;" : "=l"(d) : "l"(a), "l"(b), "l"(c));
    return d;
}

// -------------------- prelude: build M from qweights -----------------------
__global__ void build_M_kernel(const float* __restrict__ qw /* [2][4][3] */) {
    __shared__ float Ur[16][16];
    __shared__ float Ui[16][16];
    int t = threadIdx.x;               // 256 threads

    {   int z = t >> 4, c = t & 15;
        Ur[z][c] = (z == c) ? 1.0f : 0.0f;
        Ui[z][c] = 0.0f; }
    __syncthreads();

    for (int l = 0; l < 2; l++) {
        for (int i = 0; i < 4; i++) {
            float phi   = qw[(l * 4 + i) * 3 + 0];
            float theta = qw[(l * 4 + i) * 3 + 1];
            float omega = qw[(l * 4 + i) * 3 + 2];
            float ct, st;  sincosf(0.5f * theta, &st, &ct);
            float ap = 0.5f * (phi + omega), am = 0.5f * (phi - omega);
            float cap, sap, cam, sam;
            sincosf(ap, &sap, &cap);
            sincosf(am, &sam, &cam);
            float g00r =  cap * ct, g00i = -sap * ct;
            float g01r = -cam * st, g01i = -sam * st;
            float g10r =  cam * st, g10i = -sam * st;
            float g11r =  cap * ct, g11i =  sap * ct;

            int p = 3 - i;
            int mask = 1 << p;
            if (t < 128) {
                int pr = t >> 4, c = t & 15;
                int z0 = ((pr >> p) << (p + 1)) | (pr & (mask - 1));
                int z1 = z0 | mask;
                float ar = Ur[z0][c], ai = Ui[z0][c];
                float br = Ur[z1][c], bi = Ui[z1][c];
                Ur[z0][c] = g00r * ar - g00i * ai + g01r * br - g01i * bi;
                Ui[z0][c] = g00r * ai + g00i * ar + g01r * bi + g01i * br;
                Ur[z1][c] = g10r * ar - g10i * ai + g11r * br - g11i * bi;
                Ui[z1][c] = g10r * ai + g10i * ar + g11r * bi + g11i * br;
            }
            __syncthreads();
        }
        {   int z = t >> 4, c = t & 15;
            int neg = 0;
            for (int i = 0; i < 3; i++) {
                int mA = 1 << (3 - i), mB = 1 << (2 - i);
                if ((z & mA) && (z & mB)) neg ^= 1;
            }
            if (neg) { Ur[z][c] = -Ur[z][c]; Ui[z][c] = -Ui[z][c]; } }
        __syncthreads();
    }

    {   int a = t >> 4, b = t & 15;
        float m = 0.0f;
        #pragma unroll
        for (int z = 0; z < 16; z++) {
            float d = (z & 8) ? -1.0f : 1.0f;
            m += d * (Ur[z][a] * Ur[z][b] + Ui[z][a] * Ui[z][b]);
        }
        g_M[a * 16 + b] = m; }
}

// -------------------- main fused kernel (4 samples / thread) ---------------
__global__ __launch_bounds__(128, 2)
void qnn_kernel(const float* __restrict__ text, const float* __restrict__ image,
                const float* __restrict__ tW1, const float* __restrict__ tb1,
                const float* __restrict__ tW2, const float* __restrict__ tb2,
                const float* __restrict__ iW1, const float* __restrict__ ib1,
                const float* __restrict__ iW2, const float* __restrict__ ib2,
                const float* __restrict__ cW1, const float* __restrict__ cb1,
                const float* __restrict__ cW2, const float* __restrict__ cb2,
                float* __restrict__ out, int B)
{
    // UNIQUE weights in shared (no duplication)
    __shared__ __align__(16) float s_iW1[3072];   // [48][64]
    __shared__ __align__(16) float s_tW1[512];    // [16][32]
    __shared__ __align__(16) float s_iW2[256];    // [64][4]
    __shared__ __align__(16) float s_tW2[128];    // [32][4]
    __shared__ __align__(16) float s_M[256];      // [16][16]
    __shared__ __align__(16) float s_ib1[64];
    __shared__ __align__(16) float s_tb1[32];
    __shared__ float s_cW1[16], s_cb1[16], s_cW2[32];
    __shared__ float s_fb[4];
    __shared__ float s_cb2[2];

    int tid = threadIdx.x;
    for (int i = tid; i < 3072; i += 128) s_iW1[i] = iW1[i];
    for (int i = tid; i < 512;  i += 128) s_tW1[i] = tW1[i];
    for (int i = tid; i < 256;  i += 128) { s_iW2[i] = iW2[i]; s_M[i] = g_M[i]; }
    if (tid < 128) s_tW2[tid] = tW2[tid];
    if (tid < 64)  s_ib1[tid] = ib1[tid];
    if (tid < 32)  { s_tb1[tid] = tb1[tid]; s_cW2[tid] = cW2[tid]; }
    if (tid < 16)  { s_cW1[tid] = cW1[tid]; s_cb1[tid] = cb1[tid]; }
    if (tid < 4)   s_fb[tid] = tb2[tid] + ib2[tid];
    if (tid < 2)   s_cb2[tid] = cb2[tid];
    __syncthreads();

    int base = blockIdx.x * 512 + tid;
    int sidx[4];
    bool has[4];
    #pragma unroll
    for (int s = 0; s < 4; s++) {
        int v = base + s * 128;
        has[s] = (v < B);
        sidx[s] = has[s] ? v : (B - 1);
    }

    float fe[4][4];
    #pragma unroll
    for (int s = 0; s < 4; s++)
        #pragma unroll
        for (int c = 0; c < 4; c++) fe[s][c] = s_fb[c];

    // ---- image MLP: 48 -> relu(64) -> 4, j-tiled 2 x 32, 4 samples ----
    {
        const float4* ip[4];
        #pragma unroll
        for (int s = 0; s < 4; s++)
            ip[s] = reinterpret_cast<const float4*>(image) + (size_t)sidx[s] * 12;
        #pragma unroll
        for (int chunk = 0; chunk < 2; chunk++) {
            int wb = chunk * 32;
            ull acc0[16], acc1[16], acc2[16], acc3[16];
            const ull* bias = reinterpret_cast<const ull*>(s_ib1) + wb / 2;
            #pragma unroll
            for (int j = 0; j < 16; j++) {
                ull b = bias[j];
                acc0[j] = b; acc1[j] = b; acc2[j] = b; acc3[j] = b;
            }
            #pragma unroll 1
            for (int kk = 0; kk < 12; kk++) {
                float4 a0 = __ldg(ip[0] + kk);
                float4 a1 = __ldg(ip[1] + kk);
                float4 a2 = __ldg(ip[2] + kk);
                float4 a3 = __ldg(ip[3] + kk);
                float av0[4] = {a0.x, a0.y, a0.z, a0.w};
                float av1[4] = {a1.x, a1.y, a1.z, a1.w};
                float av2[4] = {a2.x, a2.y, a2.z, a2.w};
                float av3[4] = {a3.x, a3.y, a3.z, a3.w};
                #pragma unroll
                for (int dk = 0; dk < 4; dk++) {
                    ull d0 = dup2(av0[dk]);
                    ull d1 = dup2(av1[dk]);
                    ull d2 = dup2(av2[dk]);
                    ull d3 = dup2(av3[dk]);
                    const ulonglong2* w2 = reinterpret_cast<const ulonglong2*>(
                        &s_iW1[(kk * 4 + dk) * 64 + wb]);
                    #pragma unroll
                    for (int j4 = 0; j4 < 8; j4++) {
                        ulonglong2 w = w2[j4];       // 4 unique weights, 4 samples
                        acc0[2 * j4]     = fma2(d0, w.x, acc0[2 * j4]);
                        acc0[2 * j4 + 1] = fma2(d0, w.y, acc0[2 * j4 + 1]);
                        acc1[2 * j4]     = fma2(d1, w.x, acc1[2 * j4]);
                        acc1[2 * j4 + 1] = fma2(d1, w.y, acc1[2 * j4 + 1]);
                        acc2[2 * j4]     = fma2(d2, w.x, acc2[2 * j4]);
                        acc2[2 * j4 + 1] = fma2(d2, w.y, acc2[2 * j4 + 1]);
                        acc3[2 * j4]     = fma2(d3, w.x, acc3[2 * j4]);
                        acc3[2 * j4 + 1] = fma2(d3, w.y, acc3[2 * j4 + 1]);
                    }
                }
            }
            // epilogue: relu + second layer; weight row loads shared by samples
            #pragma unroll
            for (int p = 0; p < 16; p++) {
                int j = wb + 2 * p;
                const float* r0 = &s_iW2[j * 4];
                const float* r1 = &s_iW2[(j + 1) * 4];
                float w0[4], w1[4];
                #pragma unroll
                for (int c = 0; c < 4; c++) { w0[c] = r0[c]; w1[c] = r1[c]; }
                float lo, hi;
                unpack2(acc0[p], lo, hi);
                lo = fmaxf(lo, 0.0f); hi = fmaxf(hi, 0.0f);
                #pragma unroll
                for (int c = 0; c < 4; c++)
                    fe[0][c] = fmaf(hi, w1[c], fmaf(lo, w0[c], fe[0][c]));
                unpack2(acc1[p], lo, hi);
                lo = fmaxf(lo, 0.0f); hi = fmaxf(hi, 0.0f);
                #pragma unroll
                for (int c = 0; c < 4; c++)
                    fe[1][c] = fmaf(hi, w1[c], fmaf(lo, w0[c], fe[1][c]));
                unpack2(acc2[p], lo, hi);
                lo = fmaxf(lo, 0.0f); hi = fmaxf(hi, 0.0f);
                #pragma unroll
                for (int c = 0; c < 4; c++)
                    fe[2][c] = fmaf(hi, w1[c], fmaf(lo, w0[c], fe[2][c]));
                unpack2(acc3[p], lo, hi);
                lo = fmaxf(lo, 0.0f); hi = fmaxf(hi, 0.0f);
                #pragma unroll
                for (int c = 0; c < 4; c++)
                    fe[3][c] = fmaf(hi, w1[c], fmaf(lo, w0[c], fe[3][c]));
            }
        }
    }

    // ---- text MLP: 16 -> relu(32) -> 4, single 32-j chunk, 4 samples ----
    {
        const float4* tp[4];
        #pragma unroll
        for (int s = 0; s < 4; s++)
            tp[s] = reinterpret_cast<const float4*>(text) + (size_t)sidx[s] * 4;
        ull acc0[16], acc1[16], acc2[16], acc3[16];
        const ull* bias = reinterpret_cast<const ull*>(s_tb1);
        #pragma unroll
        for (int j = 0; j < 16; j++) {
            ull b = bias[j];
            acc0[j] = b; acc1[j] = b; acc2[j] = b; acc3[j] = b;
        }
        #pragma unroll 1
        for (int kk = 0; kk < 4; kk++) {
            float4 a0 = __ldg(tp[0] + kk);
            float4 a1 = __ldg(tp[1] + kk);
            float4 a2 = __ldg(tp[2] + kk);
            float4 a3 = __ldg(tp[3] + kk);
            float av0[4] = {a0.x, a0.y, a0.z, a0.w};
            float av1[4] = {a1.x, a1.y, a1.z, a1.w};
            float av2[4] = {a2.x, a2.y, a2.z, a2.w};
            float av3[4] = {a3.x, a3.y, a3.z, a3.w};
            #pragma unroll
            for (int dk = 0; dk < 4; dk++) {
                ull d0 = dup2(av0[dk]);
                ull d1 = dup2(av1[dk]);
                ull d2 = dup2(av2[dk]);
                ull d3 = dup2(av3[dk]);
                const ulonglong2* w2 = reinterpret_cast<const ulonglong2*>(
                    &s_tW1[(kk * 4 + dk) * 32]);
                #pragma unroll
                for (int j4 = 0; j4 < 8; j4++) {
                    ulonglong2 w = w2[j4];
                    acc0[2 * j4]     = fma2(d0, w.x, acc0[2 * j4]);
                    acc0[2 * j4 + 1] = fma2(d0, w.y, acc0[2 * j4 + 1]);
                    acc1[2 * j4]     = fma2(d1, w.x, acc1[2 * j4]);
                    acc1[2 * j4 + 1] = fma2(d1, w.y, acc1[2 * j4 + 1]);
                    acc2[2 * j4]     = fma2(d2, w.x, acc2[2 * j4]);
                    acc2[2 * j4 + 1] = fma2(d2, w.y, acc2[2 * j4 + 1]);
                    acc3[2 * j4]     = fma2(d3, w.x, acc3[2 * j4]);
                    acc3[2 * j4 + 1] = fma2(d3, w.y, acc3[2 * j4 + 1]);
                }
            }
        }
        #pragma unroll
        for (int p = 0; p < 16; p++) {
            int j = 2 * p;
            const float* r0 = &s_tW2[j * 4];
            const float* r1 = &s_tW2[(j + 1) * 4];
            float w0[4], w1[4];
            #pragma unroll
            for (int c = 0; c < 4; c++) { w0[c] = r0[c]; w1[c] = r1[c]; }
            float lo, hi;
            unpack2(acc0[p], lo, hi);
            lo = fmaxf(lo, 0.0f); hi = fmaxf(hi, 0.0f);
            #pragma unroll
            for (int c = 0; c < 4; c++)
                fe[0][c] = fmaf(hi, w1[c], fmaf(lo, w0[c], fe[0][c]));
            unpack2(acc1[p], lo, hi);
            lo = fmaxf(lo, 0.0f); hi = fmaxf(hi, 0.0f);
            #pragma unroll
            for (int c = 0; c < 4; c++)
                fe[1][c] = fmaf(hi, w1[c], fmaf(lo, w0[c], fe[1][c]));
            unpack2(acc2[p], lo, hi);
            lo = fmaxf(lo, 0.0f); hi = fmaxf(hi, 0.0f);
            #pragma unroll
            for (int c = 0; c < 4; c++)
                fe[2][c] = fmaf(hi, w1[c], fmaf(lo, w0[c], fe[2][c]));
            unpack2(acc3[p], lo, hi);
            lo = fmaxf(lo, 0.0f); hi = fmaxf(hi, 0.0f);
            #pragma unroll
            for (int c = 0; c < 4; c++)
                fe[3][c] = fmaf(hi, w1[c], fmaf(lo, w0[c], fe[3][c]));
        }
    }

    // ---- quantum: <Z0> = v^T M v per sample; v packed by adjacent b ----
    // ref half-angle of (tf+imf)*0.5 -> angle * 0.25
    ull vp[4][8];
    #pragma unroll
    for (int s = 0; s < 4; s++) {
        float cq[4], sq[4];
        #pragma unroll
        for (int i = 0; i < 4; i++) sincosf(fe[s][i] * 0.25f, &sq[i], &cq[i]);
        float p0[4] = {cq[0]*cq[1], cq[0]*sq[1], sq[0]*cq[1], sq[0]*sq[1]};
        float p1[4] = {cq[2]*cq[3], cq[2]*sq[3], sq[2]*cq[3], sq[2]*sq[3]};
        #pragma unroll
        for (int h = 0; h < 4; h++)
            #pragma unroll
            for (int l2 = 0; l2 < 2; l2++)
                vp[s][h * 2 + l2] = pack2(p0[h] * p1[2 * l2], p0[h] * p1[2 * l2 + 1]);
    }

    float q[4] = {0.0f, 0.0f, 0.0f, 0.0f};
    #pragma unroll
    for (int a = 0; a < 16; a++) {
        const ulonglong2* mrow = reinterpret_cast<const ulonglong2*>(&s_M[a * 16]);
        ull wp[4] = {0ull, 0ull, 0ull, 0ull};
        #pragma unroll
        for (int b2 = 0; b2 < 4; b2++) {
            ulonglong2 m = mrow[b2];   // 4 unique M values shared by 4 samples
            #pragma unroll
            for (int s = 0; s < 4; s++) {
                wp[s] = fma2(vp[s][2 * b2],     m.x, wp[s]);
                wp[s] = fma2(vp[s][2 * b2 + 1], m.y, wp[s]);
            }
        }
        #pragma unroll
        for (int s = 0; s < 4; s++) {
            float wl, wh, vl, vh;
            unpack2(wp[s], wl, wh);
            unpack2(vp[s][a >> 1], vl, vh);
            float va = (a & 1) ? vh : vl;
            q[s] = fmaf(va, wl + wh, q[s]);
        }
    }

    // ---- classifier: 1 -> relu(16) -> 2 ----
    float o0[4], o1[4];
    #pragma unroll
    for (int s = 0; s < 4; s++) { o0[s] = s_cb2[0]; o1[s] = s_cb2[1]; }
    #pragma unroll
    for (int j = 0; j < 16; j++) {
        float w1v = s_cW1[j], b1v = s_cb1[j];
        float w20 = s_cW2[2 * j], w21 = s_cW2[2 * j + 1];
        #pragma unroll
        for (int s = 0; s < 4; s++) {
            float h = fmaxf(fmaf(q[s], w1v, b1v), 0.0f);
            o0[s] = fmaf(h, w20, o0[s]);
            o1[s] = fmaf(h, w21, o1[s]);
        }
    }

    float2* out2 = reinterpret_cast<float2*>(out);
    #pragma unroll
    for (int s = 0; s < 4; s++)
        if (has[s]) out2[sidx[s]] = make_float2(o0[s], o1[s]);
}

// -------------------- launch -----------------------------------------------
extern "C" void kernel_launch(void* const* d_in, const int* in_sizes, int n_in,
                              void* d_out, int out_size) {
    const float* text = (const float*)d_in[0];
    const float* image= (const float*)d_in[1];
    const float* tW1  = (const float*)d_in[2];
    const float* tb1  = (const float*)d_in[3];
    const float* tW2  = (const float*)d_in[4];
    const float* tb2  = (const float*)d_in[5];
    const float* iW1  = (const float*)d_in[6];
    const float* ib1  = (const float*)d_in[7];
    const float* iW2  = (const float*)d_in[8];
    const float* ib2  = (const float*)d_in[9];
    const float* qw   = (const float*)d_in[10];
    const float* cW1  = (const float*)d_in[11];
    const float* cb1  = (const float*)d_in[12];
    const float* cW2  = (const float*)d_in[13];
    const float* cb2  = (const float*)d_in[14];
    float* out = (float*)d_out;

    int B = in_sizes[0] / 16;

    build_M_kernel<<<1, 256>>>(qw);
    int nblk = (B + 511) / 512;
    qnn_kernel<<<nblk, 128>>>(text, image, tW1, tb1, tW2, tb2,
                              iW1, ib1, iW2, ib2, cW1, cb1, cW2, cb2,
                              out, B);
}